// round 5
// baseline (speedup 1.0000x reference)
#include <cuda_runtime.h>
#include <cuda_bf16.h>
#include <math.h>
#include <stdint.h>

// ---------------- problem constants ----------------
constexpr int T    = 2048;
constexpr int HID  = 4096;
constexpr int NH   = 32;
constexpr int DQ   = 256;
constexpr int DN   = 192;
constexpr int DR   = 64;
constexpr int DV   = 256;
constexpr int DKV  = 512;
constexpr int QLORA= 2048;
constexpr int HDQ  = NH * DQ;        // 8192
constexpr int KVW  = NH * (DN + DV); // 14336
constexpr int LATW = DKV + DR;       // 576

// ---------------- fp32 scratch ----------------
__device__ float g_qlora[(size_t)T * QLORA];
__device__ float g_latent[(size_t)T * LATW];
__device__ float g_q[(size_t)T * HDQ];
__device__ float g_kv[(size_t)T * KVW];
__device__ float g_S[(size_t)NH * T * T];
__device__ float g_O[(size_t)T * HDQ];

// ---------------- split-bf16 planes ----------------
__device__ __nv_bfloat16 g_hid_p [2][(size_t)T * HID];
__device__ __nv_bfloat16 g_wqaT  [2][(size_t)QLORA * HID];
__device__ __nv_bfloat16 g_wkvaT [2][(size_t)LATW * HID];
__device__ __nv_bfloat16 g_wqbT  [2][(size_t)HDQ * QLORA];
__device__ __nv_bfloat16 g_wkvbT [2][(size_t)KVW * DKV];
__device__ __nv_bfloat16 g_woT   [2][(size_t)HID * HDQ];
__device__ __nv_bfloat16 g_qlo_p [2][(size_t)T * QLORA];
__device__ __nv_bfloat16 g_lat_p [2][(size_t)T * DKV];
__device__ __nv_bfloat16 g_q_p   [2][(size_t)T * HDQ];
__device__ __nv_bfloat16 g_Kc_p  [2][(size_t)T * HDQ];
__device__ __nv_bfloat16 g_Vt_p  [2][(size_t)NH * DV * T];
__device__ __nv_bfloat16 g_P_p   [2][(size_t)NH * T * T];
__device__ __nv_bfloat16 g_O_p   [2][(size_t)T * HDQ];

// ---------------- helpers ----------------
__device__ __forceinline__ void splitf(float v, __nv_bfloat16& h, __nv_bfloat16& l) {
    h = __float2bfloat16_rn(v);
    l = __float2bfloat16_rn(v - __bfloat162float(h));
}

__device__ __forceinline__ void mma_bf16(float* c, const uint32_t* a, const uint32_t* b) {
    asm volatile(
        "mma.sync.aligned.m16n8k16.row.col.f32.bf16.bf16.f32 "
        "{%0,%1,%2,%3}, {%4,%5,%6,%7}, {%8,%9}, {%0,%1,%2,%3};\n"
        : "+f"(c[0]), "+f"(c[1]), "+f"(c[2]), "+f"(c[3])
        : "r"(a[0]), "r"(a[1]), "r"(a[2]), "r"(a[3]), "r"(b[0]), "r"(b[1]));
}

__device__ __forceinline__ void ldsm4(uint32_t& r0, uint32_t& r1, uint32_t& r2, uint32_t& r3, uint32_t a) {
    asm volatile("ldmatrix.sync.aligned.m8n8.x4.shared.b16 {%0,%1,%2,%3}, [%4];"
        : "=r"(r0), "=r"(r1), "=r"(r2), "=r"(r3) : "r"(a));
}

__device__ __forceinline__ void cp16(uint32_t d, const void* s) {
    asm volatile("cp.async.cg.shared.global [%0], [%1], 16;" :: "r"(d), "l"(s));
}

// ============================================================================
// Split-bf16 GEMM: C = A @ B^T on hi/lo planes (row m / row n hold k).
// Block 256x128, BK=32, 256 threads (8 warps, warp tile 64x64).
// smem: 2 stages x (A 2x20480 + B 2x10240) = 122880 bytes; 1 CTA/SM.
// Per warp-chunk: 32 ldsm4 + 192 HMMA (3 split terms).
// Requires M % 256 == 0, K % 32 == 0.
// ============================================================================
constexpr int APL    = 256 * 80;               // 20480: one A plane
constexpr int BPL    = 128 * 80;               // 10240: one B plane
constexpr int BOFF   = 2 * APL;                // B planes start
constexpr int STAGE  = 2 * APL + 2 * BPL;      // 61440
constexpr int SMEM_GEMM = 2 * STAGE;           // 122880

__global__ __launch_bounds__(256, 1) void tgemm_pl(
    const __nv_bfloat16* __restrict__ Ah, const __nv_bfloat16* __restrict__ Al,
    const __nv_bfloat16* __restrict__ Bh, const __nv_bfloat16* __restrict__ Bl,
    float* __restrict__ C,
    int M, int N, int K, int lda, int ldb, int ldc,
    long sA, long sB, long sC, int causal, int truncK)
{
    const int bx = blockIdx.x, by = blockIdx.y;
    if (causal && bx >= 2 * (by + 1)) return;       // block fully above diagonal
    Ah += (long)blockIdx.z * sA;  Al += (long)blockIdx.z * sA;
    Bh += (long)blockIdx.z * sB;  Bl += (long)blockIdx.z * sB;
    C  += (long)blockIdx.z * sC;
    if (truncK) { int ke = (by + 1) * 256; if (ke < K) K = ke; }

    extern __shared__ char smem[];
    const uint32_t sb = (uint32_t)__cvta_generic_to_shared(smem);

    const int tid = threadIdx.x, lane = tid & 31, warp = tid >> 5;
    const int wm = warp & 3, wn = warp >> 2;     // 4 row-groups x 2 col-groups
    const int g = lane >> 2, t4 = lane & 3;

    // ldmatrix lane offsets (80B row stride, conflict-free)
    const int lr  = (lane & 7) + ((lane >> 3) & 1) * 8;
    const int lkb = (lane >> 4) * 16;
    const uint32_t aB = sb + (uint32_t)((wm * 64 + lr) * 80 + lkb);
    const uint32_t bB = sb + (uint32_t)(BOFF + (wn * 64 + lr) * 80 + lkb);

    float acc[4][8][4] = {};
    const int nchunks = K / 32;
    const int Nm1 = N - 1;

    auto load_chunk = [&](int i, uint32_t st) {
        const int k0 = i * 32;
        #pragma unroll
        for (int p = 0; p < 4; p++) {            // A: 256 rows x 4 x 16B
            int id = tid + p * 256;
            int row = id >> 2, c4 = id & 3;
            uint32_t dst = sb + st + (uint32_t)(row * 80 + c4 * 16);
            long aoff = (long)(by * 256 + row) * lda + k0 + c4 * 8;
            cp16(dst,       Ah + aoff);
            cp16(dst + APL, Al + aoff);
        }
        #pragma unroll
        for (int p = 0; p < 2; p++) {            // B: 128 rows x 4 x 16B
            int id = tid + p * 256;
            int row = id >> 2, c4 = id & 3;
            uint32_t dst = sb + st + (uint32_t)(BOFF + row * 80 + c4 * 16);
            int nr = bx * 128 + row; if (nr > Nm1) nr = Nm1;
            long boff = (long)nr * ldb + k0 + c4 * 8;
            cp16(dst,       Bh + boff);
            cp16(dst + BPL, Bl + boff);
        }
    };

    load_chunk(0, 0);
    asm volatile("cp.async.commit_group;");
    if (nchunks > 1) load_chunk(1, STAGE);
    asm volatile("cp.async.commit_group;");

    for (int i = 0; i < nchunks; i++) {
        asm volatile("cp.async.wait_group 1;");
        __syncthreads();

        const uint32_t sof = (uint32_t)((i & 1) * STAGE);
        #pragma unroll
        for (int ks = 0; ks < 2; ks++) {
            uint32_t ah[4][4], al[4][4];
            #pragma unroll
            for (int mt = 0; mt < 4; mt++) {
                uint32_t ad = aB + sof + (uint32_t)(mt * 16 * 80 + ks * 32);
                ldsm4(ah[mt][0], ah[mt][1], ah[mt][2], ah[mt][3], ad);
                ldsm4(al[mt][0], al[mt][1], al[mt][2], al[mt][3], ad + APL);
            }
            #pragma unroll
            for (int hf = 0; hf < 2; hf++) {
                uint32_t bh[4][2], bl[4][2];
                #pragma unroll
                for (int p = 0; p < 2; p++) {
                    uint32_t bd = bB + sof + (uint32_t)((hf * 32 + p * 16) * 80 + ks * 32);
                    uint32_t x0, x1, x2, x3;
                    ldsm4(x0, x1, x2, x3, bd);
                    bh[2*p][0] = x0; bh[2*p+1][0] = x1; bh[2*p][1] = x2; bh[2*p+1][1] = x3;
                    ldsm4(x0, x1, x2, x3, bd + BPL);
                    bl[2*p][0] = x0; bl[2*p+1][0] = x1; bl[2*p][1] = x2; bl[2*p+1][1] = x3;
                }
                #pragma unroll
                for (int mt = 0; mt < 4; mt++) {
                    #pragma unroll
                    for (int nt = 0; nt < 4; nt++) {
                        float* c = acc[mt][hf * 4 + nt];
                        mma_bf16(c, ah[mt], bh[nt]);
                        mma_bf16(c, ah[mt], bl[nt]);
                        mma_bf16(c, al[mt], bh[nt]);
                    }
                }
            }
        }
        __syncthreads();

        if (i + 2 < nchunks) load_chunk(i + 2, sof);
        asm volatile("cp.async.commit_group;");
    }

    // ---- epilogue ----
    #pragma unroll
    for (int mt = 0; mt < 4; mt++) {
        int r = by * 256 + wm * 64 + mt * 16 + g;
        #pragma unroll
        for (int nt = 0; nt < 8; nt++) {
            int c = bx * 128 + wn * 64 + nt * 8 + 2 * t4;
            if (c < N) {
                *(float2*)&C[(long)r * ldc + c]       = make_float2(acc[mt][nt][0], acc[mt][nt][1]);
                *(float2*)&C[(long)(r + 8) * ldc + c] = make_float2(acc[mt][nt][2], acc[mt][nt][3]);
            }
        }
    }
}

// ---------------- fp32 -> planes ----------------
__global__ void conv_pl_k(const float* __restrict__ x, __nv_bfloat16* __restrict__ h,
                          __nv_bfloat16* __restrict__ l, long n)
{
    long i = (long)blockIdx.x * blockDim.x + threadIdx.x;
    long stride = (long)gridDim.x * blockDim.x;
    for (; i < n; i += stride) {
        __nv_bfloat16 hh, ll;
        splitf(x[i], hh, ll);
        h[i] = hh; l[i] = ll;
    }
}

// ---------------- fp32 [R,C] -> planes transposed [C,R] ----------------
__global__ void conv_tr_k(const float* __restrict__ x, __nv_bfloat16* __restrict__ h,
                          __nv_bfloat16* __restrict__ l, int R, int C)
{
    __shared__ float tile[32][33];
    const int c0 = blockIdx.x * 32, rr0 = blockIdx.y * 32;
    const int tx = threadIdx.x & 31, ty = threadIdx.x >> 5;
    #pragma unroll
    for (int i = 0; i < 4; i++) {
        int r = rr0 + ty + i * 8;
        tile[ty + i * 8][tx] = x[(long)r * C + c0 + tx];
    }
    __syncthreads();
    #pragma unroll
    for (int i = 0; i < 4; i++) {
        int c = c0 + ty + i * 8;
        float v = tile[tx][ty + i * 8];
        long o = (long)c * R + rr0 + tx;
        __nv_bfloat16 hh, ll;
        splitf(v, hh, ll);
        h[o] = hh; l[o] = ll;
    }
}

// ---------------- RMSNorm fp32 -> planes ----------------
__global__ void rmsnorm_pl_k(const float* __restrict__ x, const float* __restrict__ w,
                             __nv_bfloat16* __restrict__ h, __nv_bfloat16* __restrict__ l,
                             int N, int ldin)
{
    const float* p = x + (long)blockIdx.x * ldin;
    __shared__ float red[8];
    __shared__ float bc;
    const int lane = threadIdx.x & 31, wid = threadIdx.x >> 5;

    float s = 0.f;
    for (int j = threadIdx.x; j < N; j += blockDim.x) { float v = p[j]; s += v * v; }
    #pragma unroll
    for (int o = 16; o; o >>= 1) s += __shfl_xor_sync(0xffffffffu, s, o);
    if (lane == 0) red[wid] = s;
    __syncthreads();
    if (threadIdx.x == 0) {
        float v = 0.f;
        for (int wI = 0; wI < 8; wI++) v += red[wI];
        bc = rsqrtf(v / N + 1e-6f);
    }
    __syncthreads();
    float r = bc;
    long ob = (long)blockIdx.x * N;
    for (int j = threadIdx.x; j < N; j += blockDim.x) {
        __nv_bfloat16 hh, ll;
        splitf(p[j] * r * w[j], hh, ll);
        h[ob + j] = hh; l[ob + j] = ll;
    }
}

// ---------------- rope k_pe in-place ----------------
__global__ void rope_kpe_k(float* __restrict__ lat, const int* __restrict__ pos)
{
    const int tt = blockIdx.x, i = threadIdx.x;
    double inv = pow(10000.0, -(double)i / 32.0);
    double sd, cd;
    sincos((double)pos[tt] * inv, &sd, &cd);
    float c = (float)cd, s = (float)sd;
    float* p = lat + (long)tt * LATW + DKV;
    float x1 = p[i], x2 = p[i + 32];
    p[i]      = x1 * c - x2 * s;
    p[i + 32] = x2 * c + x1 * s;
}

// ---------------- q: rope fused + planes ----------------
__global__ void rope_conv_q_k(const float* __restrict__ q, const int* __restrict__ pos,
                              __nv_bfloat16* __restrict__ h, __nv_bfloat16* __restrict__ l)
{
    const int tt = blockIdx.x;
    __shared__ float cs[32], sn[32];
    if (threadIdx.x < 32) {
        double inv = pow(10000.0, -(double)threadIdx.x / 32.0);
        double sd, cd;
        sincos((double)pos[tt] * inv, &sd, &cd);
        cs[threadIdx.x] = (float)cd; sn[threadIdx.x] = (float)sd;
    }
    __syncthreads();
    const float* row = q + (long)tt * HDQ;
    long ob = (long)tt * HDQ;
    for (int x = threadIdx.x; x < HDQ; x += blockDim.x) {
        int d = x & 255;
        float v;
        if (d < DN)            v = row[x];
        else if (d < DN + 32) { int i = d - DN;       v = row[x] * cs[i] - row[x + 32] * sn[i]; }
        else                  { int i = d - DN - 32;  v = row[x] * cs[i] + row[x - 32] * sn[i]; }
        __nv_bfloat16 hh, ll;
        splitf(v, hh, ll);
        h[ob + x] = hh; l[ob + x] = ll;
    }
}

// ---------------- K assembly -> planes ----------------
__global__ void build_K_pl_k(const float* __restrict__ kv, const float* __restrict__ lat,
                             __nv_bfloat16* __restrict__ h, __nv_bfloat16* __restrict__ l)
{
    const int tt = blockIdx.x;
    long ob = (long)tt * HDQ;
    for (int x = threadIdx.x; x < HDQ; x += blockDim.x) {
        int hd = x >> 8, d = x & 255;
        float v = (d < DN) ? kv[(long)tt * KVW + hd * (DN + DV) + d]
                           : lat[(long)tt * LATW + DKV + (d - DN)];
        __nv_bfloat16 hh, ll;
        splitf(v, hh, ll);
        h[ob + x] = hh; l[ob + x] = ll;
    }
}

// ---------------- V transpose per head -> planes [h][DV][T] ----------------
__global__ void transpose_v_pl_k(const float* __restrict__ kv,
                                 __nv_bfloat16* __restrict__ h, __nv_bfloat16* __restrict__ l)
{
    __shared__ float tile[32][33];
    const int d0 = blockIdx.x * 32, t0 = blockIdx.y * 32, hd = blockIdx.z;
    const int tx = threadIdx.x & 31, ty = threadIdx.x >> 5;
    #pragma unroll
    for (int i = 0; i < 4; i++) {
        int tr = t0 + ty + i * 8;
        tile[ty + i * 8][tx] = kv[(long)tr * KVW + hd * (DN + DV) + DN + d0 + tx];
    }
    __syncthreads();
    #pragma unroll
    for (int i = 0; i < 4; i++) {
        int d = d0 + ty + i * 8;
        float v = tile[tx][ty + i * 8];
        long o = (long)hd * DV * T + (long)d * T + t0 + tx;
        __nv_bfloat16 hh, ll;
        splitf(v, hh, ll);
        h[o] = hh; l[o] = ll;
    }
}

// ---------------- causal softmax: fp32 scores -> P planes ----------------
__global__ void softmax_pl_k(float* __restrict__ S,
                             __nv_bfloat16* __restrict__ Ph, __nv_bfloat16* __restrict__ Pl)
{
    const float scale = 0.0625f;
    const int tt = blockIdx.x, hd = blockIdx.y;
    long rb = ((long)hd * T + tt) * (long)T;
    float* row = S + rb;
    const int n = tt + 1;
    __shared__ float red[8];
    __shared__ float bc;
    const int lane = threadIdx.x & 31, wid = threadIdx.x >> 5;

    float m = -3.4e38f;
    for (int j = threadIdx.x; j < n; j += blockDim.x) m = fmaxf(m, row[j]);
    #pragma unroll
    for (int o = 16; o; o >>= 1) m = fmaxf(m, __shfl_xor_sync(0xffffffffu, m, o));
    if (lane == 0) red[wid] = m;
    __syncthreads();
    if (threadIdx.x == 0) {
        float v = red[0];
        for (int wI = 1; wI < 8; wI++) v = fmaxf(v, red[wI]);
        bc = v;
    }
    __syncthreads();
    m = bc;
    __syncthreads();

    float s = 0.f;
    for (int j = threadIdx.x; j < n; j += blockDim.x) {
        float e = expf((row[j] - m) * scale);
        row[j] = e;
        s += e;
    }
    #pragma unroll
    for (int o = 16; o; o >>= 1) s += __shfl_xor_sync(0xffffffffu, s, o);
    if (lane == 0) red[wid] = s;
    __syncthreads();
    if (threadIdx.x == 0) {
        float v = 0.f;
        for (int wI = 0; wI < 8; wI++) v += red[wI];
        bc = 1.f / v;
    }
    __syncthreads();
    float inv = bc;
    for (int j = threadIdx.x; j < n; j += blockDim.x) {
        __nv_bfloat16 hh, ll;
        splitf(row[j] * inv, hh, ll);
        Ph[rb + j] = hh; Pl[rb + j] = ll;
    }
    const __nv_bfloat16 z = __float2bfloat16_rn(0.f);
    for (int j = n + threadIdx.x; j < T; j += blockDim.x) { Ph[rb + j] = z; Pl[rb + j] = z; }
}

// ---------------- launch ----------------
extern "C" void kernel_launch(void* const* d_in, const int* in_sizes, int n_in,
                              void* d_out, int out_size)
{
    (void)in_sizes; (void)n_in; (void)out_size;
    const float* hidden = (const float*)d_in[0];
    const int*   pos    = (const int*)  d_in[1];
    const float* wq_a   = (const float*)d_in[2];
    const float* q_ln   = (const float*)d_in[3];
    const float* wq_b   = (const float*)d_in[4];
    const float* wkv_a  = (const float*)d_in[5];
    const float* kv_ln  = (const float*)d_in[6];
    const float* wkv_b  = (const float*)d_in[7];
    const float* wo     = (const float*)d_in[8];
    float* out = (float*)d_out;

    cudaFuncSetAttribute(tgemm_pl, cudaFuncAttributeMaxDynamicSharedMemorySize, SMEM_GEMM);

    float *qlora, *latent, *q, *kv, *S, *O;
    cudaGetSymbolAddress((void**)&qlora,  g_qlora);
    cudaGetSymbolAddress((void**)&latent, g_latent);
    cudaGetSymbolAddress((void**)&q,      g_q);
    cudaGetSymbolAddress((void**)&kv,     g_kv);
    cudaGetSymbolAddress((void**)&S,      g_S);
    cudaGetSymbolAddress((void**)&O,      g_O);

    __nv_bfloat16 *hidp, *wqaT, *wkvaT, *wqbT, *wkvbT, *woT,
                  *qlop, *latp, *qp, *Kcp, *Vtp, *Pp, *Op;
    cudaGetSymbolAddress((void**)&hidp,  g_hid_p);
    cudaGetSymbolAddress((void**)&wqaT,  g_wqaT);
    cudaGetSymbolAddress((void**)&wkvaT, g_wkvaT);
    cudaGetSymbolAddress((void**)&wqbT,  g_wqbT);
    cudaGetSymbolAddress((void**)&wkvbT, g_wkvbT);
    cudaGetSymbolAddress((void**)&woT,   g_woT);
    cudaGetSymbolAddress((void**)&qlop,  g_qlo_p);
    cudaGetSymbolAddress((void**)&latp,  g_lat_p);
    cudaGetSymbolAddress((void**)&qp,    g_q_p);
    cudaGetSymbolAddress((void**)&Kcp,   g_Kc_p);
    cudaGetSymbolAddress((void**)&Vtp,   g_Vt_p);
    cudaGetSymbolAddress((void**)&Pp,    g_P_p);
    cudaGetSymbolAddress((void**)&Op,    g_O_p);

    #define PL(base, n) (base), ((base) + (size_t)(n))

    const size_t nHid = (size_t)T * HID,    nWqa = (size_t)QLORA * HID;
    const size_t nWkva= (size_t)LATW * HID, nWqb = (size_t)HDQ * QLORA;
    const size_t nWkvb= (size_t)KVW * DKV,  nWo  = (size_t)HID * HDQ;
    const size_t nQlo = (size_t)T * QLORA,  nLat = (size_t)T * DKV;
    const size_t nQ   = (size_t)T * HDQ,    nP   = (size_t)NH * T * T;
    const size_t nVt  = (size_t)NH * DV * T;

    dim3 blk(256);

    // ---- weight conversion + transpose ----
    conv_tr_k<<<dim3(QLORA/32, HID/32), blk>>>(wq_a,  PL(wqaT,  nWqa), HID, QLORA);
    conv_tr_k<<<dim3(LATW/32,  HID/32), blk>>>(wkv_a, PL(wkvaT, nWkva), HID, LATW);
    conv_tr_k<<<dim3(HDQ/32, QLORA/32), blk>>>(wq_b,  PL(wqbT,  nWqb), QLORA, HDQ);
    conv_tr_k<<<dim3(KVW/32,  DKV/32),  blk>>>(wkv_b, PL(wkvbT, nWkvb), DKV, KVW);
    conv_tr_k<<<dim3(HID/32,  HDQ/32),  blk>>>(wo,    PL(woT,   nWo),  HDQ, HID);
    conv_pl_k<<<2048, 256>>>(hidden, PL(hidp, nHid), (long)nHid);

    // ---- down projections ----
    tgemm_pl<<<dim3(QLORA/128, T/256), blk, SMEM_GEMM>>>(PL(hidp, nHid), PL(wqaT, nWqa),
        qlora, T, QLORA, HID, HID, HID, QLORA, 0, 0, 0, 0, 0);
    tgemm_pl<<<dim3((LATW+127)/128, T/256), blk, SMEM_GEMM>>>(PL(hidp, nHid), PL(wkvaT, nWkva),
        latent, T, LATW, HID, HID, HID, LATW, 0, 0, 0, 0, 0);

    // ---- norms + rope(k_pe) ----
    rmsnorm_pl_k<<<T, 256>>>(qlora, q_ln, PL(qlop, nQlo), QLORA, QLORA);
    rope_kpe_k<<<T, 32>>>(latent, pos);
    rmsnorm_pl_k<<<T, 256>>>(latent, kv_ln, PL(latp, nLat), DKV, LATW);

    // ---- up projections ----
    tgemm_pl<<<dim3(HDQ/128, T/256), blk, SMEM_GEMM>>>(PL(qlop, nQlo), PL(wqbT, nWqb),
        q, T, HDQ, QLORA, QLORA, QLORA, HDQ, 0, 0, 0, 0, 0);
    tgemm_pl<<<dim3(KVW/128, T/256), blk, SMEM_GEMM>>>(PL(latp, nLat), PL(wkvbT, nWkvb),
        kv, T, KVW, DKV, DKV, DKV, KVW, 0, 0, 0, 0, 0);

    // ---- q rope + planes; K assembly; V transpose ----
    rope_conv_q_k<<<T, 256>>>(q, pos, PL(qp, nQ));
    build_K_pl_k<<<T, 256>>>(kv, latent, PL(Kcp, nQ));
    transpose_v_pl_k<<<dim3(DV/32, T/32, NH), blk>>>(kv, PL(Vtp, nVt));

    // ---- scores (batched over heads, causal block skip) ----
    tgemm_pl<<<dim3(T/128, T/256, NH), blk, SMEM_GEMM>>>(
        qp,  qp + nQ,  Kcp, Kcp + nQ, S,
        T, T, DQ, HDQ, HDQ, T, (long)DQ, (long)DQ, (long)T * T, 1, 0);

    // ---- softmax -> P planes ----
    softmax_pl_k<<<dim3(T, NH), 256>>>(S, PL(Pp, nP));

    // ---- PV (causal K truncation) ----
    tgemm_pl<<<dim3(DV/128, T/256, NH), blk, SMEM_GEMM>>>(
        Pp, Pp + nP, Vtp, Vtp + nVt, O,
        T, DV, T, T, T, HDQ, (long)T * T, (long)DV * T, (long)DV, 0, 1);

    // ---- O planes + final projection ----
    conv_pl_k<<<2048, 256>>>(O, PL(Op, nQ), (long)nQ);
    tgemm_pl<<<dim3(HID/128, T/256), blk, SMEM_GEMM>>>(PL(Op, nQ), PL(woT, nWo),
        out, T, HID, HDQ, HDQ, HDQ, HID, 0, 0, 0, 0, 0);

    #undef PL
}

// round 6
// speedup vs baseline: 1.1146x; 1.1146x over previous
#include <cuda_runtime.h>
#include <cuda_bf16.h>
#include <math.h>
#include <stdint.h>

// ---------------- problem constants ----------------
constexpr int T    = 2048;
constexpr int HID  = 4096;
constexpr int NH   = 32;
constexpr int DQ   = 256;
constexpr int DN   = 192;
constexpr int DR   = 64;
constexpr int DV   = 256;
constexpr int DKV  = 512;
constexpr int QLORA= 2048;
constexpr int HDQ  = NH * DQ;        // 8192
constexpr int KVW  = NH * (DN + DV); // 14336
constexpr int LATW = DKV + DR;       // 576

// ---------------- fp32 scratch ----------------
__device__ float g_qlora[(size_t)T * QLORA];
__device__ float g_latent[(size_t)T * LATW];
__device__ float g_q[(size_t)T * HDQ];
__device__ float g_kv[(size_t)T * KVW];
__device__ float g_O[(size_t)T * HDQ];

// ---------------- split-bf16 planes ----------------
__device__ __nv_bfloat16 g_hid_p [2][(size_t)T * HID];
__device__ __nv_bfloat16 g_wqaT  [2][(size_t)QLORA * HID];
__device__ __nv_bfloat16 g_wkvaT [2][(size_t)LATW * HID];
__device__ __nv_bfloat16 g_wqbT  [2][(size_t)HDQ * QLORA];
__device__ __nv_bfloat16 g_wkvbT [2][(size_t)KVW * DKV];
__device__ __nv_bfloat16 g_woT   [2][(size_t)HID * HDQ];
__device__ __nv_bfloat16 g_qlo_p [2][(size_t)T * QLORA];
__device__ __nv_bfloat16 g_lat_p [2][(size_t)T * DKV];
__device__ __nv_bfloat16 g_q_p   [2][(size_t)T * HDQ];
__device__ __nv_bfloat16 g_Kc_p  [2][(size_t)T * HDQ];
__device__ __nv_bfloat16 g_Vt_p  [2][(size_t)NH * DV * T];
__device__ __nv_bfloat16 g_O_p   [2][(size_t)T * HDQ];

// ---------------- helpers ----------------
__device__ __forceinline__ void splitf(float v, __nv_bfloat16& h, __nv_bfloat16& l) {
    h = __float2bfloat16_rn(v);
    l = __float2bfloat16_rn(v - __bfloat162float(h));
}

__device__ __forceinline__ uint32_t pack2(__nv_bfloat16 a, __nv_bfloat16 b) {
    return ((uint32_t)__bfloat16_as_ushort(b) << 16) | (uint32_t)__bfloat16_as_ushort(a);
}

__device__ __forceinline__ void mma_bf16(float* c, const uint32_t* a, const uint32_t* b) {
    asm volatile(
        "mma.sync.aligned.m16n8k16.row.col.f32.bf16.bf16.f32 "
        "{%0,%1,%2,%3}, {%4,%5,%6,%7}, {%8,%9}, {%0,%1,%2,%3};\n"
        : "+f"(c[0]), "+f"(c[1]), "+f"(c[2]), "+f"(c[3])
        : "r"(a[0]), "r"(a[1]), "r"(a[2]), "r"(a[3]), "r"(b[0]), "r"(b[1]));
}

__device__ __forceinline__ void ldsm4(uint32_t& r0, uint32_t& r1, uint32_t& r2, uint32_t& r3, uint32_t a) {
    asm volatile("ldmatrix.sync.aligned.m8n8.x4.shared.b16 {%0,%1,%2,%3}, [%4];"
        : "=r"(r0), "=r"(r1), "=r"(r2), "=r"(r3) : "r"(a));
}

__device__ __forceinline__ void cp16(uint32_t d, const void* s) {
    asm volatile("cp.async.cg.shared.global [%0], [%1], 16;" :: "r"(d), "l"(s));
}

// ============================================================================
// Split-bf16 GEMM (R3 config): C = A @ B^T on hi/lo planes.
// Block 128x128, BK=32, 256 threads (8 warps, 64x32 warp tiles), 2 CTAs/SM.
// ============================================================================
constexpr int TILE_B   = 128 * 80;
constexpr int STAGE_B  = 4 * TILE_B;
constexpr int SMEM_GEMM = 2 * STAGE_B;   // 81920

__global__ __launch_bounds__(256, 2) void tgemm_pl(
    const __nv_bfloat16* __restrict__ Ah, const __nv_bfloat16* __restrict__ Al,
    const __nv_bfloat16* __restrict__ Bh, const __nv_bfloat16* __restrict__ Bl,
    float* __restrict__ C,
    int M, int N, int K, int lda, int ldb, int ldc,
    long sA, long sB, long sC)
{
    const int bx = blockIdx.x, by = blockIdx.y;
    Ah += (long)blockIdx.z * sA;  Al += (long)blockIdx.z * sA;
    Bh += (long)blockIdx.z * sB;  Bl += (long)blockIdx.z * sB;
    C  += (long)blockIdx.z * sC;

    extern __shared__ char smem[];
    const uint32_t sb = (uint32_t)__cvta_generic_to_shared(smem);

    const int tid = threadIdx.x, lane = tid & 31, warp = tid >> 5;
    const int wm = warp & 1, wn = warp >> 1;
    const int g = lane >> 2, t4 = lane & 3;

    const int r0 = tid >> 2, c4 = tid & 3;
    const int Nm1 = N - 1;

    const int lr  = (lane & 7) + ((lane >> 3) & 1) * 8;
    const int lkb = (lane >> 4) * 16;
    const uint32_t aBase = sb + (uint32_t)((wm * 64 + lr) * 80 + lkb);
    const uint32_t bBase = sb + (uint32_t)(2 * TILE_B + (wn * 32 + lr) * 80 + lkb);

    float acc[4][4][4] = {};
    const int nchunks = K / 32;

    {
        #pragma unroll
        for (int c = 0; c < 2; c++) {
            int row = r0 + c * 64;
            uint32_t ds = sb + (uint32_t)(row * 80 + c4 * 16);
            long aoff = (long)(by * 128 + row) * lda + c4 * 8;
            cp16(ds,              Ah + aoff);
            cp16(ds + TILE_B,     Al + aoff);
            int nr = bx * 128 + row; if (nr > Nm1) nr = Nm1;
            long boff = (long)nr * ldb + c4 * 8;
            cp16(ds + 2 * TILE_B, Bh + boff);
            cp16(ds + 3 * TILE_B, Bl + boff);
        }
        asm volatile("cp.async.commit_group;");
    }

    for (int i = 0; i < nchunks; i++) {
        if (i + 1 < nchunks) {
            const int k0 = (i + 1) * 32;
            const uint32_t st = (uint32_t)(((i + 1) & 1) * STAGE_B);
            #pragma unroll
            for (int c = 0; c < 2; c++) {
                int row = r0 + c * 64;
                uint32_t ds = sb + st + (uint32_t)(row * 80 + c4 * 16);
                long aoff = (long)(by * 128 + row) * lda + k0 + c4 * 8;
                cp16(ds,              Ah + aoff);
                cp16(ds + TILE_B,     Al + aoff);
                int nr = bx * 128 + row; if (nr > Nm1) nr = Nm1;
                long boff = (long)nr * ldb + k0 + c4 * 8;
                cp16(ds + 2 * TILE_B, Bh + boff);
                cp16(ds + 3 * TILE_B, Bl + boff);
            }
        }
        asm volatile("cp.async.commit_group;");
        asm volatile("cp.async.wait_group 1;");
        __syncthreads();

        const uint32_t sof = (uint32_t)((i & 1) * STAGE_B);
        #pragma unroll
        for (int ks = 0; ks < 2; ks++) {
            uint32_t bh[4][2], bl[4][2];
            #pragma unroll
            for (int p = 0; p < 2; p++) {
                uint32_t ad = bBase + sof + (uint32_t)(p * 16 * 80 + ks * 32);
                uint32_t x0, x1, x2, x3;
                ldsm4(x0, x1, x2, x3, ad);
                bh[2*p][0] = x0; bh[2*p+1][0] = x1; bh[2*p][1] = x2; bh[2*p+1][1] = x3;
                ldsm4(x0, x1, x2, x3, ad + TILE_B);
                bl[2*p][0] = x0; bl[2*p+1][0] = x1; bl[2*p][1] = x2; bl[2*p+1][1] = x3;
            }
            #pragma unroll
            for (int mt = 0; mt < 4; mt++) {
                uint32_t ah[4], al[4];
                uint32_t ad = aBase + sof + (uint32_t)(mt * 16 * 80 + ks * 32);
                ldsm4(ah[0], ah[1], ah[2], ah[3], ad);
                ldsm4(al[0], al[1], al[2], al[3], ad + TILE_B);
                #pragma unroll
                for (int nt = 0; nt < 4; nt++) {
                    mma_bf16(acc[mt][nt], ah, bh[nt]);
                    mma_bf16(acc[mt][nt], ah, bl[nt]);
                    mma_bf16(acc[mt][nt], al, bh[nt]);
                }
            }
        }
        __syncthreads();
    }

    #pragma unroll
    for (int mt = 0; mt < 4; mt++) {
        int r = by * 128 + wm * 64 + mt * 16 + g;
        #pragma unroll
        for (int nt = 0; nt < 4; nt++) {
            int c = bx * 128 + wn * 32 + nt * 8 + 2 * t4;
            if (c < N) {
                *(float2*)&C[(long)r * ldc + c]       = make_float2(acc[mt][nt][0], acc[mt][nt][1]);
                *(float2*)&C[(long)(r + 8) * ldc + c] = make_float2(acc[mt][nt][2], acc[mt][nt][3]);
            }
        }
    }
}

// ============================================================================
// Fused flash attention (split-bf16, 3-term): per block = (q-tile 128, head).
// 8 warps, warp = 16 q-rows. Online softmax in registers; P never hits memory.
// smem: QK double-buffered d-chunks (2 x 40960) / PV V-chunks (69632) union.
// ============================================================================
constexpr int FA_SMEM = 81920;
constexpr int QPL = 10240;           // one 128x(32d) plane @80B stride
constexpr int VPL = 128 * 272;       // 34816: one 128dv x 128kv plane @272B stride

__global__ __launch_bounds__(256, 1) void flash_k(
    const __nv_bfloat16* __restrict__ Qh, const __nv_bfloat16* __restrict__ Ql,
    const __nv_bfloat16* __restrict__ Kh, const __nv_bfloat16* __restrict__ Kl,
    const __nv_bfloat16* __restrict__ Vh, const __nv_bfloat16* __restrict__ Vl,
    float* __restrict__ O)
{
    const int qi = gridDim.x - 1 - blockIdx.x;   // heavy tiles first
    const int h  = blockIdx.y;

    extern __shared__ char smem[];
    const uint32_t sb = (uint32_t)__cvta_generic_to_shared(smem);

    const int tid = threadIdx.x, lane = tid & 31, w = tid >> 5;
    const int g = lane >> 2, t4 = lane & 3;
    const int lr  = (lane & 7) + ((lane >> 3) & 1) * 8;
    const int lkb = (lane >> 4) * 16;

    float oacc[32][4];
    #pragma unroll
    for (int i = 0; i < 32; i++)
        #pragma unroll
        for (int c = 0; c < 4; c++) oacc[i][c] = 0.f;
    float m0 = -1e30f, m1 = -1e30f, l0 = 0.f, l1 = 0.f;

    const float scale = 0.0625f;

    for (int j = 0; j <= qi; j++) {
        float sacc[16][4] = {};

        // ---------------- QK: 8 d-chunks of 32, double-buffered ----------------
        auto load_qk = [&](int i, uint32_t st) {
            const int d = i * 32;
            #pragma unroll
            for (int p = 0; p < 2; p++) {
                int id = tid + p * 256;
                int row = id >> 2, cc = id & 3;
                uint32_t dst = sb + st + (uint32_t)(row * 80 + cc * 16);
                size_t qo = (size_t)(qi * 128 + row) * HDQ + h * DQ + d + cc * 8;
                cp16(dst,           Qh + qo);
                cp16(dst + QPL,     Ql + qo);
                size_t ko = (size_t)(j * 128 + row) * HDQ + h * DQ + d + cc * 8;
                cp16(dst + 2 * QPL, Kh + ko);
                cp16(dst + 3 * QPL, Kl + ko);
            }
        };

        load_qk(0, 0);
        asm volatile("cp.async.commit_group;");
        load_qk(1, 4 * QPL);
        asm volatile("cp.async.commit_group;");

        for (int i = 0; i < 8; i++) {
            asm volatile("cp.async.wait_group 1;");
            __syncthreads();
            const uint32_t st = (uint32_t)((i & 1) * 4 * QPL);
            #pragma unroll
            for (int ks = 0; ks < 2; ks++) {
                uint32_t ah[4], al[4];
                uint32_t ad = sb + st + (uint32_t)((w * 16 + lr) * 80 + lkb + ks * 32);
                ldsm4(ah[0], ah[1], ah[2], ah[3], ad);
                ldsm4(al[0], al[1], al[2], al[3], ad + QPL);
                #pragma unroll
                for (int p = 0; p < 8; p++) {
                    uint32_t bh[2][2], bl[2][2], x0, x1, x2, x3;
                    uint32_t bd = sb + st + (uint32_t)(2 * QPL + (p * 16 + lr) * 80 + lkb + ks * 32);
                    ldsm4(x0, x1, x2, x3, bd);
                    bh[0][0] = x0; bh[1][0] = x1; bh[0][1] = x2; bh[1][1] = x3;
                    ldsm4(x0, x1, x2, x3, bd + QPL);
                    bl[0][0] = x0; bl[1][0] = x1; bl[0][1] = x2; bl[1][1] = x3;
                    #pragma unroll
                    for (int q2 = 0; q2 < 2; q2++) {
                        float* c = sacc[p * 2 + q2];
                        mma_bf16(c, ah, bh[q2]);
                        mma_bf16(c, ah, bl[q2]);
                        mma_bf16(c, al, bh[q2]);
                    }
                }
            }
            __syncthreads();
            if (i + 2 < 8) load_qk(i + 2, st);
            asm volatile("cp.async.commit_group;");
        }
        asm volatile("cp.async.wait_group 0;");

        // ---------------- softmax (registers) ----------------
        #pragma unroll
        for (int nt = 0; nt < 16; nt++)
            #pragma unroll
            for (int c = 0; c < 4; c++) sacc[nt][c] *= scale;

        if (j == qi) {
            const int rr0 = w * 16 + g, rr1 = rr0 + 8;
            #pragma unroll
            for (int nt = 0; nt < 16; nt++) {
                int col = nt * 8 + 2 * t4;
                if (col     > rr0) sacc[nt][0] = -1e30f;
                if (col + 1 > rr0) sacc[nt][1] = -1e30f;
                if (col     > rr1) sacc[nt][2] = -1e30f;
                if (col + 1 > rr1) sacc[nt][3] = -1e30f;
            }
        }

        float tm0 = -1e30f, tm1 = -1e30f;
        #pragma unroll
        for (int nt = 0; nt < 16; nt++) {
            tm0 = fmaxf(tm0, fmaxf(sacc[nt][0], sacc[nt][1]));
            tm1 = fmaxf(tm1, fmaxf(sacc[nt][2], sacc[nt][3]));
        }
        tm0 = fmaxf(tm0, __shfl_xor_sync(0xffffffffu, tm0, 1));
        tm0 = fmaxf(tm0, __shfl_xor_sync(0xffffffffu, tm0, 2));
        tm1 = fmaxf(tm1, __shfl_xor_sync(0xffffffffu, tm1, 1));
        tm1 = fmaxf(tm1, __shfl_xor_sync(0xffffffffu, tm1, 2));

        float nm0 = fmaxf(m0, tm0), nm1 = fmaxf(m1, tm1);
        float a0 = expf(m0 - nm0), a1 = expf(m1 - nm1);
        m0 = nm0; m1 = nm1;

        float s0 = 0.f, s1 = 0.f;
        #pragma unroll
        for (int nt = 0; nt < 16; nt++) {
            sacc[nt][0] = expf(sacc[nt][0] - m0); s0 += sacc[nt][0];
            sacc[nt][1] = expf(sacc[nt][1] - m0); s0 += sacc[nt][1];
            sacc[nt][2] = expf(sacc[nt][2] - m1); s1 += sacc[nt][2];
            sacc[nt][3] = expf(sacc[nt][3] - m1); s1 += sacc[nt][3];
        }
        s0 += __shfl_xor_sync(0xffffffffu, s0, 1);
        s0 += __shfl_xor_sync(0xffffffffu, s0, 2);
        s1 += __shfl_xor_sync(0xffffffffu, s1, 1);
        s1 += __shfl_xor_sync(0xffffffffu, s1, 2);
        l0 = l0 * a0 + s0;
        l1 = l1 * a1 + s1;

        #pragma unroll
        for (int i = 0; i < 32; i++) {
            oacc[i][0] *= a0; oacc[i][1] *= a0;
            oacc[i][2] *= a1; oacc[i][3] *= a1;
        }

        // ---------------- P fragments from sacc (A-operand layout) ----------------
        uint32_t Pf0[8][4], Pf1[8][4];
        #pragma unroll
        for (int ks = 0; ks < 8; ks++) {
            #pragma unroll
            for (int hf = 0; hf < 2; hf++) {
                const float* c = sacc[2 * ks + hf];
                __nv_bfloat16 ha, la, hb, lb;
                splitf(c[0], ha, la); splitf(c[1], hb, lb);
                Pf0[ks][hf * 2]     = pack2(ha, hb);
                Pf1[ks][hf * 2]     = pack2(la, lb);
                splitf(c[2], ha, la); splitf(c[3], hb, lb);
                Pf0[ks][hf * 2 + 1] = pack2(ha, hb);
                Pf1[ks][hf * 2 + 1] = pack2(la, lb);
            }
        }

        // ---------------- PV: 2 dv-chunks of 128 ----------------
        #pragma unroll
        for (int dvc = 0; dvc < 2; dvc++) {
            __syncthreads();
            #pragma unroll
            for (int p = 0; p < 8; p++) {
                int id = tid + p * 256;
                int row = id >> 4, cc = id & 15;
                uint32_t dst = sb + (uint32_t)(row * 272 + cc * 16);
                size_t vo = (size_t)h * DV * T + (size_t)(dvc * 128 + row) * T + j * 128 + cc * 8;
                cp16(dst,       Vh + vo);
                cp16(dst + VPL, Vl + vo);
            }
            asm volatile("cp.async.commit_group;");
            asm volatile("cp.async.wait_group 0;");
            __syncthreads();

            #pragma unroll
            for (int ks = 0; ks < 8; ks++) {
                #pragma unroll
                for (int p = 0; p < 8; p++) {
                    uint32_t vh[2][2], vl[2][2], x0, x1, x2, x3;
                    uint32_t bd = sb + (uint32_t)((p * 16 + lr) * 272 + lkb + ks * 32);
                    ldsm4(x0, x1, x2, x3, bd);
                    vh[0][0] = x0; vh[1][0] = x1; vh[0][1] = x2; vh[1][1] = x3;
                    ldsm4(x0, x1, x2, x3, bd + VPL);
                    vl[0][0] = x0; vl[1][0] = x1; vl[0][1] = x2; vl[1][1] = x3;
                    #pragma unroll
                    for (int q2 = 0; q2 < 2; q2++) {
                        float* c = oacc[dvc * 16 + p * 2 + q2];
                        mma_bf16(c, Pf0[ks], vh[q2]);
                        mma_bf16(c, Pf0[ks], vl[q2]);
                        mma_bf16(c, Pf1[ks], vh[q2]);
                    }
                }
            }
        }
        __syncthreads();   // protect V smem before next tile's QK loads
    }

    // ---------------- epilogue ----------------
    const float i0 = 1.f / l0, i1 = 1.f / l1;
    const int r0 = qi * 128 + w * 16 + g;
    float* o0 = O + (size_t)r0 * HDQ + h * DV;
    float* o1 = o0 + (size_t)8 * HDQ;
    #pragma unroll
    for (int nt = 0; nt < 32; nt++) {
        int c = nt * 8 + 2 * t4;
        *(float2*)&o0[c] = make_float2(oacc[nt][0] * i0, oacc[nt][1] * i0);
        *(float2*)&o1[c] = make_float2(oacc[nt][2] * i1, oacc[nt][3] * i1);
    }
}

// ---------------- fp32 -> planes ----------------
__global__ void conv_pl_k(const float* __restrict__ x, __nv_bfloat16* __restrict__ h,
                          __nv_bfloat16* __restrict__ l, long n)
{
    long i = (long)blockIdx.x * blockDim.x + threadIdx.x;
    long stride = (long)gridDim.x * blockDim.x;
    for (; i < n; i += stride) {
        __nv_bfloat16 hh, ll;
        splitf(x[i], hh, ll);
        h[i] = hh; l[i] = ll;
    }
}

// ---------------- fp32 [R,C] -> planes transposed [C,R] ----------------
__global__ void conv_tr_k(const float* __restrict__ x, __nv_bfloat16* __restrict__ h,
                          __nv_bfloat16* __restrict__ l, int R, int C)
{
    __shared__ float tile[32][33];
    const int c0 = blockIdx.x * 32, rr0 = blockIdx.y * 32;
    const int tx = threadIdx.x & 31, ty = threadIdx.x >> 5;
    #pragma unroll
    for (int i = 0; i < 4; i++) {
        int r = rr0 + ty + i * 8;
        tile[ty + i * 8][tx] = x[(long)r * C + c0 + tx];
    }
    __syncthreads();
    #pragma unroll
    for (int i = 0; i < 4; i++) {
        int c = c0 + ty + i * 8;
        float v = tile[tx][ty + i * 8];
        long o = (long)c * R + rr0 + tx;
        __nv_bfloat16 hh, ll;
        splitf(v, hh, ll);
        h[o] = hh; l[o] = ll;
    }
}

// ---------------- RMSNorm fp32 -> planes ----------------
__global__ void rmsnorm_pl_k(const float* __restrict__ x, const float* __restrict__ w,
                             __nv_bfloat16* __restrict__ h, __nv_bfloat16* __restrict__ l,
                             int N, int ldin)
{
    const float* p = x + (long)blockIdx.x * ldin;
    __shared__ float red[8];
    __shared__ float bc;
    const int lane = threadIdx.x & 31, wid = threadIdx.x >> 5;

    float s = 0.f;
    for (int j = threadIdx.x; j < N; j += blockDim.x) { float v = p[j]; s += v * v; }
    #pragma unroll
    for (int o = 16; o; o >>= 1) s += __shfl_xor_sync(0xffffffffu, s, o);
    if (lane == 0) red[wid] = s;
    __syncthreads();
    if (threadIdx.x == 0) {
        float v = 0.f;
        for (int wI = 0; wI < 8; wI++) v += red[wI];
        bc = rsqrtf(v / N + 1e-6f);
    }
    __syncthreads();
    float r = bc;
    long ob = (long)blockIdx.x * N;
    for (int j = threadIdx.x; j < N; j += blockDim.x) {
        __nv_bfloat16 hh, ll;
        splitf(p[j] * r * w[j], hh, ll);
        h[ob + j] = hh; l[ob + j] = ll;
    }
}

// ---------------- rope k_pe in-place ----------------
__global__ void rope_kpe_k(float* __restrict__ lat, const int* __restrict__ pos)
{
    const int tt = blockIdx.x, i = threadIdx.x;
    double inv = pow(10000.0, -(double)i / 32.0);
    double sd, cd;
    sincos((double)pos[tt] * inv, &sd, &cd);
    float c = (float)cd, s = (float)sd;
    float* p = lat + (long)tt * LATW + DKV;
    float x1 = p[i], x2 = p[i + 32];
    p[i]      = x1 * c - x2 * s;
    p[i + 32] = x2 * c + x1 * s;
}

// ---------------- q: rope fused + planes ----------------
__global__ void rope_conv_q_k(const float* __restrict__ q, const int* __restrict__ pos,
                              __nv_bfloat16* __restrict__ h, __nv_bfloat16* __restrict__ l)
{
    const int tt = blockIdx.x;
    __shared__ float cs[32], sn[32];
    if (threadIdx.x < 32) {
        double inv = pow(10000.0, -(double)threadIdx.x / 32.0);
        double sd, cd;
        sincos((double)pos[tt] * inv, &sd, &cd);
        cs[threadIdx.x] = (float)cd; sn[threadIdx.x] = (float)sd;
    }
    __syncthreads();
    const float* row = q + (long)tt * HDQ;
    long ob = (long)tt * HDQ;
    for (int x = threadIdx.x; x < HDQ; x += blockDim.x) {
        int d = x & 255;
        float v;
        if (d < DN)            v = row[x];
        else if (d < DN + 32) { int i = d - DN;       v = row[x] * cs[i] - row[x + 32] * sn[i]; }
        else                  { int i = d - DN - 32;  v = row[x] * cs[i] + row[x - 32] * sn[i]; }
        __nv_bfloat16 hh, ll;
        splitf(v, hh, ll);
        h[ob + x] = hh; l[ob + x] = ll;
    }
}

// ---------------- K assembly -> planes ----------------
__global__ void build_K_pl_k(const float* __restrict__ kv, const float* __restrict__ lat,
                             __nv_bfloat16* __restrict__ h, __nv_bfloat16* __restrict__ l)
{
    const int tt = blockIdx.x;
    long ob = (long)tt * HDQ;
    for (int x = threadIdx.x; x < HDQ; x += blockDim.x) {
        int hd = x >> 8, d = x & 255;
        float v = (d < DN) ? kv[(long)tt * KVW + hd * (DN + DV) + d]
                           : lat[(long)tt * LATW + DKV + (d - DN)];
        __nv_bfloat16 hh, ll;
        splitf(v, hh, ll);
        h[ob + x] = hh; l[ob + x] = ll;
    }
}

// ---------------- V transpose per head -> planes [h][DV][T] ----------------
__global__ void transpose_v_pl_k(const float* __restrict__ kv,
                                 __nv_bfloat16* __restrict__ h, __nv_bfloat16* __restrict__ l)
{
    __shared__ float tile[32][33];
    const int d0 = blockIdx.x * 32, t0 = blockIdx.y * 32, hd = blockIdx.z;
    const int tx = threadIdx.x & 31, ty = threadIdx.x >> 5;
    #pragma unroll
    for (int i = 0; i < 4; i++) {
        int tr = t0 + ty + i * 8;
        tile[ty + i * 8][tx] = kv[(long)tr * KVW + hd * (DN + DV) + DN + d0 + tx];
    }
    __syncthreads();
    #pragma unroll
    for (int i = 0; i < 4; i++) {
        int d = d0 + ty + i * 8;
        float v = tile[tx][ty + i * 8];
        long o = (long)hd * DV * T + (long)d * T + t0 + tx;
        __nv_bfloat16 hh, ll;
        splitf(v, hh, ll);
        h[o] = hh; l[o] = ll;
    }
}

// ---------------- launch ----------------
extern "C" void kernel_launch(void* const* d_in, const int* in_sizes, int n_in,
                              void* d_out, int out_size)
{
    (void)in_sizes; (void)n_in; (void)out_size;
    const float* hidden = (const float*)d_in[0];
    const int*   pos    = (const int*)  d_in[1];
    const float* wq_a   = (const float*)d_in[2];
    const float* q_ln   = (const float*)d_in[3];
    const float* wq_b   = (const float*)d_in[4];
    const float* wkv_a  = (const float*)d_in[5];
    const float* kv_ln  = (const float*)d_in[6];
    const float* wkv_b  = (const float*)d_in[7];
    const float* wo     = (const float*)d_in[8];
    float* out = (float*)d_out;

    cudaFuncSetAttribute(tgemm_pl, cudaFuncAttributeMaxDynamicSharedMemorySize, SMEM_GEMM);
    cudaFuncSetAttribute(flash_k,  cudaFuncAttributeMaxDynamicSharedMemorySize, FA_SMEM);

    float *qlora, *latent, *q, *kv, *O;
    cudaGetSymbolAddress((void**)&qlora,  g_qlora);
    cudaGetSymbolAddress((void**)&latent, g_latent);
    cudaGetSymbolAddress((void**)&q,      g_q);
    cudaGetSymbolAddress((void**)&kv,     g_kv);
    cudaGetSymbolAddress((void**)&O,      g_O);

    __nv_bfloat16 *hidp, *wqaT, *wkvaT, *wqbT, *wkvbT, *woT,
                  *qlop, *latp, *qp, *Kcp, *Vtp, *Op;
    cudaGetSymbolAddress((void**)&hidp,  g_hid_p);
    cudaGetSymbolAddress((void**)&wqaT,  g_wqaT);
    cudaGetSymbolAddress((void**)&wkvaT, g_wkvaT);
    cudaGetSymbolAddress((void**)&wqbT,  g_wqbT);
    cudaGetSymbolAddress((void**)&wkvbT, g_wkvbT);
    cudaGetSymbolAddress((void**)&woT,   g_woT);
    cudaGetSymbolAddress((void**)&qlop,  g_qlo_p);
    cudaGetSymbolAddress((void**)&latp,  g_lat_p);
    cudaGetSymbolAddress((void**)&qp,    g_q_p);
    cudaGetSymbolAddress((void**)&Kcp,   g_Kc_p);
    cudaGetSymbolAddress((void**)&Vtp,   g_Vt_p);
    cudaGetSymbolAddress((void**)&Op,    g_O_p);

    #define PL(base, n) (base), ((base) + (size_t)(n))

    const size_t nHid = (size_t)T * HID,    nWqa = (size_t)QLORA * HID;
    const size_t nWkva= (size_t)LATW * HID, nWqb = (size_t)HDQ * QLORA;
    const size_t nWkvb= (size_t)KVW * DKV,  nWo  = (size_t)HID * HDQ;
    const size_t nQlo = (size_t)T * QLORA,  nLat = (size_t)T * DKV;
    const size_t nQ   = (size_t)T * HDQ;
    const size_t nVt  = (size_t)NH * DV * T;

    dim3 blk(256);

    // ---- weight conversion + transpose ----
    conv_tr_k<<<dim3(QLORA/32, HID/32), blk>>>(wq_a,  PL(wqaT,  nWqa), HID, QLORA);
    conv_tr_k<<<dim3(LATW/32,  HID/32), blk>>>(wkv_a, PL(wkvaT, nWkva), HID, LATW);
    conv_tr_k<<<dim3(HDQ/32, QLORA/32), blk>>>(wq_b,  PL(wqbT,  nWqb), QLORA, HDQ);
    conv_tr_k<<<dim3(KVW/32,  DKV/32),  blk>>>(wkv_b, PL(wkvbT, nWkvb), DKV, KVW);
    conv_tr_k<<<dim3(HID/32,  HDQ/32),  blk>>>(wo,    PL(woT,   nWo),  HDQ, HID);
    conv_pl_k<<<2048, 256>>>(hidden, PL(hidp, nHid), (long)nHid);

    // ---- down projections ----
    tgemm_pl<<<dim3(QLORA/128, T/128), blk, SMEM_GEMM>>>(PL(hidp, nHid), PL(wqaT, nWqa),
        qlora, T, QLORA, HID, HID, HID, QLORA, 0, 0, 0);
    tgemm_pl<<<dim3((LATW+127)/128, T/128), blk, SMEM_GEMM>>>(PL(hidp, nHid), PL(wkvaT, nWkva),
        latent, T, LATW, HID, HID, HID, LATW, 0, 0, 0);

    // ---- norms + rope(k_pe) ----
    rmsnorm_pl_k<<<T, 256>>>(qlora, q_ln, PL(qlop, nQlo), QLORA, QLORA);
    rope_kpe_k<<<T, 32>>>(latent, pos);
    rmsnorm_pl_k<<<T, 256>>>(latent, kv_ln, PL(latp, nLat), DKV, LATW);

    // ---- up projections ----
    tgemm_pl<<<dim3(HDQ/128, T/128), blk, SMEM_GEMM>>>(PL(qlop, nQlo), PL(wqbT, nWqb),
        q, T, HDQ, QLORA, QLORA, QLORA, HDQ, 0, 0, 0);
    tgemm_pl<<<dim3(KVW/128, T/128), blk, SMEM_GEMM>>>(PL(latp, nLat), PL(wkvbT, nWkvb),
        kv, T, KVW, DKV, DKV, DKV, KVW, 0, 0, 0);

    // ---- q rope + planes; K assembly; V transpose ----
    rope_conv_q_k<<<T, 256>>>(q, pos, PL(qp, nQ));
    build_K_pl_k<<<T, 256>>>(kv, latent, PL(Kcp, nQ));
    transpose_v_pl_k<<<dim3(DV/32, T/32, NH), blk>>>(kv, PL(Vtp, nVt));

    // ---- fused flash attention ----
    flash_k<<<dim3(T/128, NH), blk, FA_SMEM>>>(
        PL(qp, nQ), PL(Kcp, nQ), PL(Vtp, nVt), O);

    // ---- O planes + final projection ----
    conv_pl_k<<<2048, 256>>>(O, PL(Op, nQ), (long)nQ);
    tgemm_pl<<<dim3(HID/128, T/128), blk, SMEM_GEMM>>>(PL(Op, nQ), PL(woT, nWo),
        out, T, HID, HDQ, HDQ, HDQ, HID, 0, 0, 0);

    #undef PL
}